// round 1
// baseline (speedup 1.0000x reference)
#include <cuda_runtime.h>

#define NN 100000
#define NE 3200000
#define CO 13
#define NEG 0.2f

// ---------------- scratch (static device arrays; no allocation) -------------
__device__ __align__(16) float g_h1[NN * 64];   // layer1 features [N,2,32]
__device__ float g_s1s[NN * 2];                 // layer1 src scores
__device__ float g_s1d[NN * 2];                 // layer1 dst scores
__device__ float g_es1[NN * 2];                 // layer1 self-edge e
__device__ float g_mx1[NN * 2];                 // layer1 segment max
__device__ float g_dn1[NN * 2];                 // layer1 softmax denom (edges only)
__device__ __align__(16) float g_nm1[NN * 64];  // layer1 numerator
__device__ __align__(16) float g_h2[NN * 64];   // relu(layer1 out) = layer2 input
__device__ float g_hL[NN * 26];                 // layer2 features [N,2,13]
__device__ float g_s2s[NN * 2];
__device__ float g_s2d[NN * 2];
__device__ float g_es2[NN * 2];
__device__ float g_mx2[NN * 2];
__device__ float g_dn2[NN * 2];
__device__ float g_nm2[NN * 26];

__device__ __forceinline__ float lrelu(float v) { return v > 0.f ? v : NEG * v; }

// float atomic max valid for mixed signs
__device__ __forceinline__ void atomicMaxF(float* a, float v) {
    if (v >= 0.f) atomicMax((int*)a, __float_as_int(v));
    else          atomicMin((unsigned int*)a, __float_as_uint(v));
}

// ---------------- layer 1 node prologue -------------------------------------
__global__ void nodeA1(const float* __restrict__ x, const float* __restrict__ W1,
                       const float* __restrict__ a1s, const float* __restrict__ a1d) {
    __shared__ float sW[12 * 64];
    __shared__ float sA[128];  // [0:64) a_src flat, [64:128) a_dst flat
    for (int i = threadIdx.x; i < 768; i += blockDim.x) sW[i] = W1[i];
    if (threadIdx.x < 64) { sA[threadIdx.x] = a1s[threadIdx.x]; sA[64 + threadIdx.x] = a1d[threadIdx.x]; }
    __syncthreads();
    int n = blockIdx.x * blockDim.x + threadIdx.x;
    if (n >= NN) return;

    float xv[12];
#pragma unroll
    for (int i = 0; i < 12; i++) xv[i] = x[n * 12 + i];

    float h[64];
#pragma unroll
    for (int j = 0; j < 64; j++) {
        float acc = 0.f;
#pragma unroll
        for (int i = 0; i < 12; i++) acc += xv[i] * sW[i * 64 + j];
        h[j] = acc;
    }

    float ss0 = 0.f, ss1 = 0.f, sd0 = 0.f, sd1 = 0.f;
#pragma unroll
    for (int f = 0; f < 32; f++) {
        ss0 += h[f] * sA[f];
        ss1 += h[32 + f] * sA[32 + f];
        sd0 += h[f] * sA[64 + f];
        sd1 += h[32 + f] * sA[96 + f];
    }

    float4* h1v = reinterpret_cast<float4*>(g_h1) + n * 16;
    float4* nmv = reinterpret_cast<float4*>(g_nm1) + n * 16;
#pragma unroll
    for (int q = 0; q < 16; q++) {
        h1v[q] = make_float4(h[4 * q], h[4 * q + 1], h[4 * q + 2], h[4 * q + 3]);
        nmv[q] = make_float4(0.f, 0.f, 0.f, 0.f);
    }
    g_s1s[2 * n] = ss0; g_s1s[2 * n + 1] = ss1;
    g_s1d[2 * n] = sd0; g_s1d[2 * n + 1] = sd1;
    float e0 = lrelu(ss0 + sd0), e1 = lrelu(ss1 + sd1);
    g_es1[2 * n] = e0; g_es1[2 * n + 1] = e1;
    g_mx1[2 * n] = e0; g_mx1[2 * n + 1] = e1;   // self-loop seeds the max
    g_dn1[2 * n] = 0.f; g_dn1[2 * n + 1] = 0.f;
}

// ---------------- edge max (layer selected by pointers) ----------------------
__global__ void edgeMax(const int* __restrict__ src, const int* __restrict__ dst,
                        const float* __restrict__ ssrc, const float* __restrict__ sdst,
                        float* __restrict__ mx) {
    int e = blockIdx.x * blockDim.x + threadIdx.x;
    if (e >= NE) return;
    int s = src[e], d = dst[e];
    float e0 = lrelu(ssrc[2 * s] + sdst[2 * d]);
    float e1 = lrelu(ssrc[2 * s + 1] + sdst[2 * d + 1]);
    atomicMaxF(&mx[2 * d], e0);
    atomicMaxF(&mx[2 * d + 1], e1);
}

// ---------------- layer1 edge aggregate (warp per edge, 64 feats) ------------
__global__ void edgeAgg1(const int* __restrict__ src, const int* __restrict__ dst) {
    int w = (blockIdx.x * blockDim.x + threadIdx.x) >> 5;
    int lane = threadIdx.x & 31;
    if (w >= NE) return;
    int s = src[w], d = dst[w];
    float e0 = lrelu(g_s1s[2 * s] + g_s1d[2 * d]);
    float e1 = lrelu(g_s1s[2 * s + 1] + g_s1d[2 * d + 1]);
    float p0 = __expf(e0 - g_mx1[2 * d]);
    float p1 = __expf(e1 - g_mx1[2 * d + 1]);
    if (lane == 0) { atomicAdd(&g_dn1[2 * d], p0); atomicAdd(&g_dn1[2 * d + 1], p1); }
    float v0 = g_h1[s * 64 + lane] * p0;
    atomicAdd(&g_nm1[d * 64 + lane], v0);
    float v1 = g_h1[s * 64 + 32 + lane] * p1;
    atomicAdd(&g_nm1[d * 64 + 32 + lane], v1);
}

// ---------------- layer1 node epilogue: self loop + normalize + relu ---------
__global__ void nodeB1(const float* __restrict__ b1) {
    int n = blockIdx.x * blockDim.x + threadIdx.x;
    if (n >= NN) return;
    float p0 = __expf(g_es1[2 * n] - g_mx1[2 * n]);
    float p1 = __expf(g_es1[2 * n + 1] - g_mx1[2 * n + 1]);
    float i0 = 1.f / (g_dn1[2 * n] + p0 + 1e-16f);
    float i1 = 1.f / (g_dn1[2 * n + 1] + p1 + 1e-16f);
#pragma unroll
    for (int f = 0; f < 32; f++) {
        float o0 = (g_nm1[n * 64 + f] + p0 * g_h1[n * 64 + f]) * i0 + b1[f];
        float o1 = (g_nm1[n * 64 + 32 + f] + p1 * g_h1[n * 64 + 32 + f]) * i1 + b1[32 + f];
        g_h2[n * 64 + f] = o0 > 0.f ? o0 : 0.f;
        g_h2[n * 64 + 32 + f] = o1 > 0.f ? o1 : 0.f;
    }
}

// ---------------- layer 2 node prologue --------------------------------------
__global__ void nodeA2(const float* __restrict__ W2,
                       const float* __restrict__ a2s, const float* __restrict__ a2d) {
    __shared__ float sW[64 * 26];
    __shared__ float sA[52];  // [0:26) a_src, [26:52) a_dst
    for (int i = threadIdx.x; i < 64 * 26; i += blockDim.x) sW[i] = W2[i];
    if (threadIdx.x < 26) { sA[threadIdx.x] = a2s[threadIdx.x]; sA[26 + threadIdx.x] = a2d[threadIdx.x]; }
    __syncthreads();
    int n = blockIdx.x * blockDim.x + threadIdx.x;
    if (n >= NN) return;

    float acc[26];
#pragma unroll
    for (int j = 0; j < 26; j++) acc[j] = 0.f;
    const float4* h2v = reinterpret_cast<const float4*>(g_h2) + n * 16;
#pragma unroll
    for (int q = 0; q < 16; q++) {
        float4 hv = h2v[q];
#pragma unroll
        for (int j = 0; j < 26; j++) {
            acc[j] += hv.x * sW[(4 * q) * 26 + j];
            acc[j] += hv.y * sW[(4 * q + 1) * 26 + j];
            acc[j] += hv.z * sW[(4 * q + 2) * 26 + j];
            acc[j] += hv.w * sW[(4 * q + 3) * 26 + j];
        }
    }
    float ss0 = 0.f, ss1 = 0.f, sd0 = 0.f, sd1 = 0.f;
#pragma unroll
    for (int f = 0; f < 13; f++) {
        ss0 += acc[f] * sA[f];
        ss1 += acc[13 + f] * sA[13 + f];
        sd0 += acc[f] * sA[26 + f];
        sd1 += acc[13 + f] * sA[39 + f];
    }
#pragma unroll
    for (int j = 0; j < 26; j++) { g_hL[n * 26 + j] = acc[j]; g_nm2[n * 26 + j] = 0.f; }
    g_s2s[2 * n] = ss0; g_s2s[2 * n + 1] = ss1;
    g_s2d[2 * n] = sd0; g_s2d[2 * n + 1] = sd1;
    float e0 = lrelu(ss0 + sd0), e1 = lrelu(ss1 + sd1);
    g_es2[2 * n] = e0; g_es2[2 * n + 1] = e1;
    g_mx2[2 * n] = e0; g_mx2[2 * n + 1] = e1;
    g_dn2[2 * n] = 0.f; g_dn2[2 * n + 1] = 0.f;
}

// ---------------- layer2 edge aggregate (warp per edge, 26 feats) -------------
__global__ void edgeAgg2(const int* __restrict__ src, const int* __restrict__ dst) {
    int w = (blockIdx.x * blockDim.x + threadIdx.x) >> 5;
    int lane = threadIdx.x & 31;
    if (w >= NE) return;
    int s = src[w], d = dst[w];
    float e0 = lrelu(g_s2s[2 * s] + g_s2d[2 * d]);
    float e1 = lrelu(g_s2s[2 * s + 1] + g_s2d[2 * d + 1]);
    float p0 = __expf(e0 - g_mx2[2 * d]);
    float p1 = __expf(e1 - g_mx2[2 * d + 1]);
    if (lane == 0) { atomicAdd(&g_dn2[2 * d], p0); atomicAdd(&g_dn2[2 * d + 1], p1); }
    if (lane < 26) {
        float p = (lane < 13) ? p0 : p1;
        atomicAdd(&g_nm2[d * 26 + lane], p * g_hL[s * 26 + lane]);
    }
}

// ---------------- layer2 epilogue: normalize, mean heads, sigmoid, constraint -
__global__ void nodeB2(const float* __restrict__ b2, const float* __restrict__ R,
                       float* __restrict__ out) {
    __shared__ float sR[CO * CO];
    __shared__ float sB[CO];
    if (threadIdx.x < CO * CO) sR[threadIdx.x] = R[threadIdx.x];
    if (threadIdx.x < CO) sB[threadIdx.x] = b2[threadIdx.x];
    __syncthreads();
    int n = blockIdx.x * blockDim.x + threadIdx.x;
    if (n >= NN) return;

    float p0 = __expf(g_es2[2 * n] - g_mx2[2 * n]);
    float p1 = __expf(g_es2[2 * n + 1] - g_mx2[2 * n + 1]);
    float i0 = 1.f / (g_dn2[2 * n] + p0 + 1e-16f);
    float i1 = 1.f / (g_dn2[2 * n + 1] + p1 + 1e-16f);

    float sig[CO];
#pragma unroll
    for (int f = 0; f < CO; f++) {
        float v0 = (g_nm2[n * 26 + f] + p0 * g_hL[n * 26 + f]) * i0;
        float v1 = (g_nm2[n * 26 + 13 + f] + p1 * g_hL[n * 26 + 13 + f]) * i1;
        float z = 0.5f * (v0 + v1) + sB[f];
        sig[f] = 1.f / (1.f + __expf(-z));
    }
#pragma unroll
    for (int i = 0; i < CO; i++) {
        float m = -1e30f;
#pragma unroll
        for (int j = 0; j < CO; j++) {
            float v = sR[i * CO + j] * sig[j];
            m = v > m ? v : m;
        }
        out[n * CO + i] = m;
    }
}

// -----------------------------------------------------------------------------
extern "C" void kernel_launch(void* const* d_in, const int* in_sizes, int n_in,
                              void* d_out, int out_size) {
    const float* x   = (const float*)d_in[0];
    const int*   ei  = (const int*)  d_in[1];
    const float* R   = (const float*)d_in[2];
    const float* W1  = (const float*)d_in[3];
    const float* a1s = (const float*)d_in[4];
    const float* a1d = (const float*)d_in[5];
    const float* b1  = (const float*)d_in[6];
    const float* W2  = (const float*)d_in[7];
    const float* a2s = (const float*)d_in[8];
    const float* a2d = (const float*)d_in[9];
    const float* b2  = (const float*)d_in[10];
    float* out = (float*)d_out;

    const int* src = ei;
    const int* dst = ei + NE;

    const int TB = 256;
    int nbN = (NN + TB - 1) / TB;
    int nbE = (NE + TB - 1) / TB;
    long long tw = (long long)NE * 32;
    int nbW = (int)((tw + TB - 1) / TB);

    // get device pointers for layer-selectable edgeMax (same kernel both layers)
    nodeA1<<<nbN, TB>>>(x, W1, a1s, a1d);
    {
        float *ps1s, *ps1d, *pmx1;
        cudaGetSymbolAddress((void**)&ps1s, g_s1s);
        cudaGetSymbolAddress((void**)&ps1d, g_s1d);
        cudaGetSymbolAddress((void**)&pmx1, g_mx1);
        edgeMax<<<nbE, TB>>>(src, dst, ps1s, ps1d, pmx1);
    }
    edgeAgg1<<<nbW, TB>>>(src, dst);
    nodeB1<<<nbN, TB>>>(b1);
    nodeA2<<<nbN, TB>>>(W2, a2s, a2d);
    {
        float *ps2s, *ps2d, *pmx2;
        cudaGetSymbolAddress((void**)&ps2s, g_s2s);
        cudaGetSymbolAddress((void**)&ps2d, g_s2d);
        cudaGetSymbolAddress((void**)&pmx2, g_mx2);
        edgeMax<<<nbE, TB>>>(src, dst, ps2s, ps2d, pmx2);
    }
    edgeAgg2<<<nbW, TB>>>(src, dst);
    nodeB2<<<nbN, TB>>>(b2, R, out);
}

// round 2
// speedup vs baseline: 2.2410x; 2.2410x over previous
#include <cuda_runtime.h>

#define NN 100000
#define NE 3200000
#define CO 13
#define NEG 0.2f

// ---------------- scratch (static device arrays) -----------------------------
__device__ __align__(16) float  g_h1[NN * 64];   // layer1 features [N,2,32]
__device__ __align__(16) float4 g_sc1[NN];       // (ss0, ss1, sd0, sd1) layer1
__device__ float  g_dn1[NN * 2];                 // layer1 softmax denom (edges only)
__device__ __align__(16) float  g_nm1[NN * 64];  // layer1 numerator
__device__ __align__(16) float  g_hL[NN * 32];   // layer2 features [N,2,13] padded to 32
__device__ __align__(16) float4 g_sc2[NN];       // layer2 scores
__device__ float  g_dn2[NN * 2];
__device__ __align__(16) float  g_nm2[NN * 32];  // layer2 numerator (padded)
__device__ unsigned g_gk1[2];                    // global max s_src keys, layer1
__device__ unsigned g_gk2[2];                    // layer2

__device__ __forceinline__ float lrelu(float v) { return v > 0.f ? v : NEG * v; }

// order-preserving float<->uint key (for atomicMax over mixed-sign floats)
__device__ __forceinline__ unsigned fkey(float f) {
    unsigned u = __float_as_uint(f);
    return ((int)u >= 0) ? (u | 0x80000000u) : ~u;
}
__device__ __forceinline__ float funkey(unsigned k) {
    return (k & 0x80000000u) ? __uint_as_float(k & 0x7fffffffu) : __uint_as_float(~k);
}

__device__ __forceinline__ void redAddV4(float* p, float4 v) {
    asm volatile("red.global.add.v4.f32 [%0], {%1,%2,%3,%4};"
                 :: "l"(p), "f"(v.x), "f"(v.y), "f"(v.z), "f"(v.w) : "memory");
}

__global__ void initG() {
    g_gk1[0] = 0u; g_gk1[1] = 0u; g_gk2[0] = 0u; g_gk2[1] = 0u;
}

// ---------------- layer 1 node prologue --------------------------------------
__global__ void __launch_bounds__(256) nodeA1(const float* __restrict__ x,
                                              const float* __restrict__ W1,
                                              const float* __restrict__ a1s,
                                              const float* __restrict__ a1d) {
    __shared__ float sW[12 * 64];
    __shared__ float sA[128];
    __shared__ float sm0[8], sm1[8];
    for (int i = threadIdx.x; i < 768; i += blockDim.x) sW[i] = W1[i];
    if (threadIdx.x < 64) { sA[threadIdx.x] = a1s[threadIdx.x]; sA[64 + threadIdx.x] = a1d[threadIdx.x]; }
    __syncthreads();
    int n = blockIdx.x * blockDim.x + threadIdx.x;
    bool valid = n < NN;
    float ss0 = -1e30f, ss1 = -1e30f;

    if (valid) {
        float xv[12];
#pragma unroll
        for (int i = 0; i < 12; i++) xv[i] = x[n * 12 + i];
        float h[64];
#pragma unroll
        for (int j = 0; j < 64; j++) {
            float acc = 0.f;
#pragma unroll
            for (int i = 0; i < 12; i++) acc += xv[i] * sW[i * 64 + j];
            h[j] = acc;
        }
        float sd0 = 0.f, sd1 = 0.f;
        ss0 = 0.f; ss1 = 0.f;
#pragma unroll
        for (int f = 0; f < 32; f++) {
            ss0 += h[f] * sA[f];
            ss1 += h[32 + f] * sA[32 + f];
            sd0 += h[f] * sA[64 + f];
            sd1 += h[32 + f] * sA[96 + f];
        }
        float4* h1v = reinterpret_cast<float4*>(g_h1) + n * 16;
        float4* nmv = reinterpret_cast<float4*>(g_nm1) + n * 16;
#pragma unroll
        for (int q = 0; q < 16; q++) {
            h1v[q] = make_float4(h[4 * q], h[4 * q + 1], h[4 * q + 2], h[4 * q + 3]);
            nmv[q] = make_float4(0.f, 0.f, 0.f, 0.f);
        }
        g_sc1[n] = make_float4(ss0, ss1, sd0, sd1);
        g_dn1[2 * n] = 0.f; g_dn1[2 * n + 1] = 0.f;
    }
    // block-reduce max of s_src per head -> global key
#pragma unroll
    for (int off = 16; off; off >>= 1) {
        ss0 = fmaxf(ss0, __shfl_xor_sync(0xffffffffu, ss0, off));
        ss1 = fmaxf(ss1, __shfl_xor_sync(0xffffffffu, ss1, off));
    }
    int wid = threadIdx.x >> 5;
    if ((threadIdx.x & 31) == 0) { sm0[wid] = ss0; sm1[wid] = ss1; }
    __syncthreads();
    if (threadIdx.x == 0) {
        float a = sm0[0], b = sm1[0];
#pragma unroll
        for (int i = 1; i < 8; i++) { a = fmaxf(a, sm0[i]); b = fmaxf(b, sm1[i]); }
        atomicMax(&g_gk1[0], fkey(a));
        atomicMax(&g_gk1[1], fkey(b));
    }
}

// ---------------- layer1 edge aggregate: 16 lanes/edge, v4 reductions --------
__global__ void __launch_bounds__(256) edgeAgg1(const int* __restrict__ src,
                                                const int* __restrict__ dst) {
    int t = blockIdx.x * 256 + threadIdx.x;
    int e = t >> 4;
    if (e >= NE) return;
    int gi = threadIdx.x & 15;
    int h = gi >> 3;
    int s = __ldg(src + e), d = __ldg(dst + e);
    float4 cs = g_sc1[s];
    float4 cd = g_sc1[d];
    float gm = funkey(g_gk1[h]);
    float ssrc = h ? cs.y : cs.x;
    float sdst = h ? cd.w : cd.z;
    float ev = lrelu(ssrc + sdst);
    float B  = lrelu(gm + sdst);
    float p = __expf(ev - B);
    if ((gi & 7) == 0) atomicAdd(&g_dn1[2 * d + h], p);
    float4 v = *(reinterpret_cast<const float4*>(g_h1 + s * 64) + gi);
    v.x *= p; v.y *= p; v.z *= p; v.w *= p;
    redAddV4(g_nm1 + d * 64 + gi * 4, v);
}

// ---------------- fused: layer1 epilogue + layer2 prologue -------------------
__global__ void __launch_bounds__(256) nodeBA(const float* __restrict__ b1,
                                              const float* __restrict__ W2,
                                              const float* __restrict__ a2s,
                                              const float* __restrict__ a2d) {
    __shared__ float sW[64 * 26];
    __shared__ float sA[52];
    __shared__ float sB[64];
    __shared__ float sm0[8], sm1[8];
    for (int i = threadIdx.x; i < 64 * 26; i += blockDim.x) sW[i] = W2[i];
    if (threadIdx.x < 26) { sA[threadIdx.x] = a2s[threadIdx.x]; sA[26 + threadIdx.x] = a2d[threadIdx.x]; }
    if (threadIdx.x < 64) sB[threadIdx.x] = b1[threadIdx.x];
    __syncthreads();
    int n = blockIdx.x * blockDim.x + threadIdx.x;
    bool valid = n < NN;
    float ms0 = -1e30f, ms1 = -1e30f;

    if (valid) {
        float4 c = g_sc1[n];
        float gm0 = funkey(g_gk1[0]), gm1 = funkey(g_gk1[1]);
        float p0 = __expf(lrelu(c.x + c.z) - lrelu(gm0 + c.z));
        float p1 = __expf(lrelu(c.y + c.w) - lrelu(gm1 + c.w));
        float i0 = 1.f / (g_dn1[2 * n] + p0);
        float i1 = 1.f / (g_dn1[2 * n + 1] + p1);

        float h2[64];
#pragma unroll
        for (int f = 0; f < 32; f++) {
            float o0 = (g_nm1[n * 64 + f]      + p0 * g_h1[n * 64 + f])      * i0 + sB[f];
            float o1 = (g_nm1[n * 64 + 32 + f] + p1 * g_h1[n * 64 + 32 + f]) * i1 + sB[32 + f];
            h2[f]      = o0 > 0.f ? o0 : 0.f;
            h2[32 + f] = o1 > 0.f ? o1 : 0.f;
        }

        float acc[26];
#pragma unroll
        for (int j = 0; j < 26; j++) acc[j] = 0.f;
#pragma unroll
        for (int i = 0; i < 64; i++) {
            float hv = h2[i];
#pragma unroll
            for (int j = 0; j < 26; j++) acc[j] += hv * sW[i * 26 + j];
        }
        float ss0 = 0.f, ss1 = 0.f, sd0 = 0.f, sd1 = 0.f;
#pragma unroll
        for (int f = 0; f < 13; f++) {
            ss0 += acc[f] * sA[f];
            ss1 += acc[13 + f] * sA[13 + f];
            sd0 += acc[f] * sA[26 + f];
            sd1 += acc[13 + f] * sA[39 + f];
        }
        float4* hv4 = reinterpret_cast<float4*>(g_hL + n * 32);
        float4* nm4 = reinterpret_cast<float4*>(g_nm2 + n * 32);
        float tmp[32];
#pragma unroll
        for (int j = 0; j < 26; j++) tmp[j] = acc[j];
#pragma unroll
        for (int j = 26; j < 32; j++) tmp[j] = 0.f;
#pragma unroll
        for (int q = 0; q < 8; q++) {
            hv4[q] = make_float4(tmp[4 * q], tmp[4 * q + 1], tmp[4 * q + 2], tmp[4 * q + 3]);
            nm4[q] = make_float4(0.f, 0.f, 0.f, 0.f);
        }
        g_sc2[n] = make_float4(ss0, ss1, sd0, sd1);
        g_dn2[2 * n] = 0.f; g_dn2[2 * n + 1] = 0.f;
        ms0 = ss0; ms1 = ss1;
    }
#pragma unroll
    for (int off = 16; off; off >>= 1) {
        ms0 = fmaxf(ms0, __shfl_xor_sync(0xffffffffu, ms0, off));
        ms1 = fmaxf(ms1, __shfl_xor_sync(0xffffffffu, ms1, off));
    }
    int wid = threadIdx.x >> 5;
    if ((threadIdx.x & 31) == 0) { sm0[wid] = ms0; sm1[wid] = ms1; }
    __syncthreads();
    if (threadIdx.x == 0) {
        float a = sm0[0], b = sm1[0];
#pragma unroll
        for (int i = 1; i < 8; i++) { a = fmaxf(a, sm0[i]); b = fmaxf(b, sm1[i]); }
        atomicMax(&g_gk2[0], fkey(a));
        atomicMax(&g_gk2[1], fkey(b));
    }
}

// ---------------- layer2 edge aggregate: 8 lanes/edge, v4 reductions ---------
__global__ void __launch_bounds__(256) edgeAgg2(const int* __restrict__ src,
                                                const int* __restrict__ dst) {
    int t = blockIdx.x * 256 + threadIdx.x;
    int e = t >> 3;
    if (e >= NE) return;
    int gi = threadIdx.x & 7;
    int s = __ldg(src + e), d = __ldg(dst + e);
    float4 cs = g_sc2[s];
    float4 cd = g_sc2[d];
    float gm0 = funkey(g_gk2[0]), gm1 = funkey(g_gk2[1]);
    float p0 = __expf(lrelu(cs.x + cd.z) - lrelu(gm0 + cd.z));
    float p1 = __expf(lrelu(cs.y + cd.w) - lrelu(gm1 + cd.w));
    if (gi == 0) {
        atomicAdd(&g_dn2[2 * d],     p0);
        atomicAdd(&g_dn2[2 * d + 1], p1);
    }
    float4 v = *(reinterpret_cast<const float4*>(g_hL + s * 32) + gi);
    int f0 = gi * 4;
    v.x *= (f0     < 13) ? p0 : p1;
    v.y *= (f0 + 1 < 13) ? p0 : p1;
    v.z *= (f0 + 2 < 13) ? p0 : p1;
    v.w *= (f0 + 3 < 13) ? p0 : p1;
    redAddV4(g_nm2 + d * 32 + f0, v);
}

// ---------------- layer2 epilogue: normalize, mean, sigmoid, constraint ------
__global__ void __launch_bounds__(256) nodeB2(const float* __restrict__ b2,
                                              const float* __restrict__ R,
                                              float* __restrict__ out) {
    __shared__ float sR[CO * CO];
    __shared__ float sB[CO];
    if (threadIdx.x < CO * CO) sR[threadIdx.x] = R[threadIdx.x];
    if (threadIdx.x < CO) sB[threadIdx.x] = b2[threadIdx.x];
    __syncthreads();
    int n = blockIdx.x * blockDim.x + threadIdx.x;
    if (n >= NN) return;

    float4 c = g_sc2[n];
    float gm0 = funkey(g_gk2[0]), gm1 = funkey(g_gk2[1]);
    float p0 = __expf(lrelu(c.x + c.z) - lrelu(gm0 + c.z));
    float p1 = __expf(lrelu(c.y + c.w) - lrelu(gm1 + c.w));
    float i0 = 1.f / (g_dn2[2 * n] + p0);
    float i1 = 1.f / (g_dn2[2 * n + 1] + p1);

    float sig[CO];
#pragma unroll
    for (int f = 0; f < CO; f++) {
        float v0 = (g_nm2[n * 32 + f]      + p0 * g_hL[n * 32 + f])      * i0;
        float v1 = (g_nm2[n * 32 + 13 + f] + p1 * g_hL[n * 32 + 13 + f]) * i1;
        float z = 0.5f * (v0 + v1) + sB[f];
        sig[f] = 1.f / (1.f + __expf(-z));
    }
#pragma unroll
    for (int i = 0; i < CO; i++) {
        float m = 0.f;
#pragma unroll
        for (int j = 0; j < CO; j++) {
            float v = sR[i * CO + j] * sig[j];
            m = v > m ? v : m;
        }
        out[n * CO + i] = m;
    }
}

// -----------------------------------------------------------------------------
extern "C" void kernel_launch(void* const* d_in, const int* in_sizes, int n_in,
                              void* d_out, int out_size) {
    const float* x   = (const float*)d_in[0];
    const int*   ei  = (const int*)  d_in[1];
    const float* R   = (const float*)d_in[2];
    const float* W1  = (const float*)d_in[3];
    const float* a1s = (const float*)d_in[4];
    const float* a1d = (const float*)d_in[5];
    const float* b1  = (const float*)d_in[6];
    const float* W2  = (const float*)d_in[7];
    const float* a2s = (const float*)d_in[8];
    const float* a2d = (const float*)d_in[9];
    const float* b2  = (const float*)d_in[10];
    float* out = (float*)d_out;

    const int* src = ei;
    const int* dst = ei + NE;

    const int TB = 256;
    int nbN  = (NN + TB - 1) / TB;
    int nbE1 = (int)(((long long)NE * 16 + TB - 1) / TB);
    int nbE2 = (int)(((long long)NE * 8  + TB - 1) / TB);

    initG<<<1, 1>>>();
    nodeA1<<<nbN, TB>>>(x, W1, a1s, a1d);
    edgeAgg1<<<nbE1, TB>>>(src, dst);
    nodeBA<<<nbN, TB>>>(b1, W2, a2s, a2d);
    edgeAgg2<<<nbE2, TB>>>(src, dst);
    nodeB2<<<nbN, TB>>>(b2, R, out);
}

// round 4
// speedup vs baseline: 3.0771x; 1.3731x over previous
#include <cuda_runtime.h>

#define NN 100000
#define NE 3200000
#define CO 13
#define NEG 0.2f
#define NB_SCAN 98          // ceil(NN/1024)

// ---------------- scratch ----------------------------------------------------
__device__ __align__(16) float  g_h1[NN * 64];   // layer1 features [N,2,32]
__device__ __align__(16) float4 g_sc1[NN];       // (ss0, ss1, sd0, sd1)
__device__ __align__(16) float  g_h2[NN * 64];   // relu(layer1 out)
__device__ __align__(16) float  g_hL[NN * 32];   // layer2 features, padded 26->32
__device__ __align__(16) float4 g_sc2[NN];
__device__ unsigned g_gk1[2], g_gk2[2];          // global max s_src keys

__device__ unsigned g_deg[NN];
__device__ unsigned g_row[NN + 1];
__device__ unsigned g_cur[NN];
__device__ unsigned g_part[NB_SCAN];
__device__ unsigned g_poff[NB_SCAN];
__device__ int      g_adj[NE];                   // src ids grouped by dst

__device__ __forceinline__ float lrelu(float v) { return v > 0.f ? v : NEG * v; }

__device__ __forceinline__ unsigned fkey(float f) {
    unsigned u = __float_as_uint(f);
    return ((int)u >= 0) ? (u | 0x80000000u) : ~u;
}
__device__ __forceinline__ float funkey(unsigned k) {
    return (k & 0x80000000u) ? __uint_as_float(k & 0x7fffffffu) : __uint_as_float(~k);
}

// ---------------- init: zero deg + global keys -------------------------------
__global__ void initZ() {
    int i = blockIdx.x * blockDim.x + threadIdx.x;
    if (i < NN) g_deg[i] = 0u;
    if (i < 2) { g_gk1[i] = 0u; g_gk2[i] = 0u; }
}

// ---------------- CSR build --------------------------------------------------
__global__ void hist(const int* __restrict__ dst) {
    int e = blockIdx.x * blockDim.x + threadIdx.x;
    if (e < NE) atomicAdd(&g_deg[dst[e]], 1u);
}

__global__ void scanA() {  // per-1024-chunk sums
    __shared__ unsigned sm[8];
    int b = blockIdx.x, t = threadIdx.x;
    int base = b * 1024 + t * 4;
    unsigned s = 0;
#pragma unroll
    for (int k = 0; k < 4; k++) if (base + k < NN) s += g_deg[base + k];
#pragma unroll
    for (int off = 16; off; off >>= 1) s += __shfl_xor_sync(0xffffffffu, s, off);
    if ((t & 31) == 0) sm[t >> 5] = s;
    __syncthreads();
    if (t == 0) {
        unsigned tot = 0;
#pragma unroll
        for (int i = 0; i < 8; i++) tot += sm[i];
        g_part[b] = tot;
    }
}

__global__ void scanB() {  // scan the NB_SCAN partials (1 block, 128 thr)
    __shared__ unsigned sh[128];
    int t = threadIdx.x;
    unsigned v = (t < NB_SCAN) ? g_part[t] : 0u;
    sh[t] = v;
    __syncthreads();
    for (int off = 1; off < 128; off <<= 1) {
        unsigned add = (t >= off) ? sh[t - off] : 0u;
        __syncthreads();
        sh[t] += add;
        __syncthreads();
    }
    if (t < NB_SCAN) g_poff[t] = sh[t] - v;   // exclusive
    if (t == 0) g_row[NN] = NE;
}

__global__ void scanC() {  // block-local exclusive scan + offset -> row/cur
    __shared__ unsigned wsum[8];
    __shared__ unsigned woff[8];
    int b = blockIdx.x, t = threadIdx.x;
    int lane = t & 31, wid = t >> 5;
    int base = b * 1024 + t * 4;
    unsigned v[4];
#pragma unroll
    for (int k = 0; k < 4; k++) v[k] = (base + k < NN) ? g_deg[base + k] : 0u;
    unsigned tot = v[0] + v[1] + v[2] + v[3];
    unsigned inc = tot;
#pragma unroll
    for (int off = 1; off < 32; off <<= 1) {
        unsigned nb = __shfl_up_sync(0xffffffffu, inc, off);
        if (lane >= off) inc += nb;
    }
    if (lane == 31) wsum[wid] = inc;
    __syncthreads();
    if (t == 0) {
        unsigned r = 0;
#pragma unroll
        for (int i = 0; i < 8; i++) { woff[i] = r; r += wsum[i]; }
    }
    __syncthreads();
    unsigned r = inc - tot + woff[wid] + g_poff[b];
#pragma unroll
    for (int k = 0; k < 4; k++) {
        if (base + k < NN) { g_row[base + k] = r; g_cur[base + k] = r; r += v[k]; }
    }
}

__global__ void scatterE(const int* __restrict__ src, const int* __restrict__ dst) {
    int e = blockIdx.x * blockDim.x + threadIdx.x;
    if (e >= NE) return;
    unsigned pos = atomicAdd(&g_cur[dst[e]], 1u);
    g_adj[pos] = src[e];
}

// ---------------- layer 1 node prologue --------------------------------------
__global__ void __launch_bounds__(256) nodeA1(const float* __restrict__ x,
                                              const float* __restrict__ W1,
                                              const float* __restrict__ a1s,
                                              const float* __restrict__ a1d) {
    __shared__ float sW[12 * 64];
    __shared__ float sA[128];
    __shared__ float sm0[8], sm1[8];
    for (int i = threadIdx.x; i < 768; i += blockDim.x) sW[i] = W1[i];
    if (threadIdx.x < 64) { sA[threadIdx.x] = a1s[threadIdx.x]; sA[64 + threadIdx.x] = a1d[threadIdx.x]; }
    __syncthreads();
    int n = blockIdx.x * blockDim.x + threadIdx.x;
    float ss0 = -1e30f, ss1 = -1e30f;

    if (n < NN) {
        float xv[12];
#pragma unroll
        for (int i = 0; i < 12; i++) xv[i] = x[n * 12 + i];
        float h[64];
#pragma unroll
        for (int j = 0; j < 64; j++) {
            float acc = 0.f;
#pragma unroll
            for (int i = 0; i < 12; i++) acc += xv[i] * sW[i * 64 + j];
            h[j] = acc;
        }
        float sd0 = 0.f, sd1 = 0.f;
        ss0 = 0.f; ss1 = 0.f;
#pragma unroll
        for (int f = 0; f < 32; f++) {
            ss0 += h[f] * sA[f];
            ss1 += h[32 + f] * sA[32 + f];
            sd0 += h[f] * sA[64 + f];
            sd1 += h[32 + f] * sA[96 + f];
        }
        float4* h1v = reinterpret_cast<float4*>(g_h1) + n * 16;
#pragma unroll
        for (int q = 0; q < 16; q++)
            h1v[q] = make_float4(h[4 * q], h[4 * q + 1], h[4 * q + 2], h[4 * q + 3]);
        g_sc1[n] = make_float4(ss0, ss1, sd0, sd1);
    }
#pragma unroll
    for (int off = 16; off; off >>= 1) {
        ss0 = fmaxf(ss0, __shfl_xor_sync(0xffffffffu, ss0, off));
        ss1 = fmaxf(ss1, __shfl_xor_sync(0xffffffffu, ss1, off));
    }
    int wid = threadIdx.x >> 5;
    if ((threadIdx.x & 31) == 0) { sm0[wid] = ss0; sm1[wid] = ss1; }
    __syncthreads();
    if (threadIdx.x == 0) {
        float a = sm0[0], b = sm1[0];
#pragma unroll
        for (int i = 1; i < 8; i++) { a = fmaxf(a, sm0[i]); b = fmaxf(b, sm1[i]); }
        atomicMax(&g_gk1[0], fkey(a));
        atomicMax(&g_gk1[1], fkey(b));
    }
}

// ---------------- layer1 CSR aggregate: warp per node, fused epilogue --------
__global__ void __launch_bounds__(256) agg1(const float* __restrict__ b1) {
    int n = (blockIdx.x * blockDim.x + threadIdx.x) >> 5;
    if (n >= NN) return;
    int lane = threadIdx.x & 31;

    float4 c = g_sc1[n];
    float gm0 = funkey(g_gk1[0]), gm1 = funkey(g_gk1[1]);
    float B0 = lrelu(gm0 + c.z), B1 = lrelu(gm1 + c.w);
    float p0s = __expf(lrelu(c.x + c.z) - B0);
    float p1s = __expf(lrelu(c.y + c.w) - B1);

    float ps = (lane < 16) ? p0s : p1s;
    float2 hs = *(const float2*)(g_h1 + n * 64 + 2 * lane);
    float accx = ps * hs.x, accy = ps * hs.y;
    float den0 = (lane == 0) ? p0s : 0.f;
    float den1 = (lane == 0) ? p1s : 0.f;

    int start = (int)g_row[n], end = (int)g_row[n + 1];
    for (int e0 = start; e0 < end; e0 += 32) {
        int idx = e0 + lane;
        int s = 0;
        float pl0 = 0.f, pl1 = 0.f;
        if (idx < end) {
            s = g_adj[idx];
            float4 cs = g_sc1[s];
            pl0 = __expf(lrelu(cs.x + c.z) - B0);
            pl1 = __expf(lrelu(cs.y + c.w) - B1);
        }
        den0 += pl0; den1 += pl1;
        int cnt = min(32, end - e0);
#pragma unroll 4
        for (int j = 0; j < cnt; j++) {
            int   sj = __shfl_sync(0xffffffffu, s, j);
            float q0 = __shfl_sync(0xffffffffu, pl0, j);
            float q1 = __shfl_sync(0xffffffffu, pl1, j);
            float pj = (lane < 16) ? q0 : q1;
            float2 v = *(const float2*)(g_h1 + sj * 64 + 2 * lane);
            accx += pj * v.x;
            accy += pj * v.y;
        }
    }
#pragma unroll
    for (int off = 16; off; off >>= 1) {
        den0 += __shfl_xor_sync(0xffffffffu, den0, off);
        den1 += __shfl_xor_sync(0xffffffffu, den1, off);
    }
    float inv = (lane < 16) ? (1.f / den0) : (1.f / den1);
    float o0 = accx * inv + b1[2 * lane];
    float o1 = accy * inv + b1[2 * lane + 1];
    float2 o = make_float2(o0 > 0.f ? o0 : 0.f, o1 > 0.f ? o1 : 0.f);
    *(float2*)(g_h2 + n * 64 + 2 * lane) = o;
}

// ---------------- layer 2 node prologue (W2 matmul + scores) -----------------
__global__ void __launch_bounds__(256) nodeA2(const float* __restrict__ W2,
                                              const float* __restrict__ a2s,
                                              const float* __restrict__ a2d) {
    __shared__ float sW[64 * 26];
    __shared__ float sA[52];
    __shared__ float sm0[8], sm1[8];
    for (int i = threadIdx.x; i < 64 * 26; i += blockDim.x) sW[i] = W2[i];
    if (threadIdx.x < 26) { sA[threadIdx.x] = a2s[threadIdx.x]; sA[26 + threadIdx.x] = a2d[threadIdx.x]; }
    __syncthreads();
    int n = blockIdx.x * blockDim.x + threadIdx.x;
    float ms0 = -1e30f, ms1 = -1e30f;

    if (n < NN) {
        float acc[26];
#pragma unroll
        for (int j = 0; j < 26; j++) acc[j] = 0.f;
        const float4* h2v = reinterpret_cast<const float4*>(g_h2) + n * 16;
#pragma unroll
        for (int q = 0; q < 16; q++) {
            float4 hv = h2v[q];
#pragma unroll
            for (int j = 0; j < 26; j++) {
                acc[j] += hv.x * sW[(4 * q) * 26 + j];
                acc[j] += hv.y * sW[(4 * q + 1) * 26 + j];
                acc[j] += hv.z * sW[(4 * q + 2) * 26 + j];
                acc[j] += hv.w * sW[(4 * q + 3) * 26 + j];
            }
        }
        float ss0 = 0.f, ss1 = 0.f, sd0 = 0.f, sd1 = 0.f;
#pragma unroll
        for (int f = 0; f < 13; f++) {
            ss0 += acc[f] * sA[f];
            ss1 += acc[13 + f] * sA[13 + f];
            sd0 += acc[f] * sA[26 + f];
            sd1 += acc[13 + f] * sA[39 + f];
        }
        float tmp[32];
#pragma unroll
        for (int j = 0; j < 26; j++) tmp[j] = acc[j];
#pragma unroll
        for (int j = 26; j < 32; j++) tmp[j] = 0.f;
        float4* hv4 = reinterpret_cast<float4*>(g_hL + n * 32);
#pragma unroll
        for (int q = 0; q < 8; q++)
            hv4[q] = make_float4(tmp[4 * q], tmp[4 * q + 1], tmp[4 * q + 2], tmp[4 * q + 3]);
        g_sc2[n] = make_float4(ss0, ss1, sd0, sd1);
        ms0 = ss0; ms1 = ss1;
    }
#pragma unroll
    for (int off = 16; off; off >>= 1) {
        ms0 = fmaxf(ms0, __shfl_xor_sync(0xffffffffu, ms0, off));
        ms1 = fmaxf(ms1, __shfl_xor_sync(0xffffffffu, ms1, off));
    }
    int wid = threadIdx.x >> 5;
    if ((threadIdx.x & 31) == 0) { sm0[wid] = ms0; sm1[wid] = ms1; }
    __syncthreads();
    if (threadIdx.x == 0) {
        float a = sm0[0], b = sm1[0];
#pragma unroll
        for (int i = 1; i < 8; i++) { a = fmaxf(a, sm0[i]); b = fmaxf(b, sm1[i]); }
        atomicMax(&g_gk2[0], fkey(a));
        atomicMax(&g_gk2[1], fkey(b));
    }
}

// ---------------- layer2 CSR aggregate + sigmoid + constraint (fused) --------
__global__ void __launch_bounds__(256) agg2(const float* __restrict__ b2,
                                            const float* __restrict__ R,
                                            float* __restrict__ out) {
    __shared__ float sR[CO * CO];
    if (threadIdx.x < CO * CO) sR[threadIdx.x] = R[threadIdx.x];
    __syncthreads();
    int n = (blockIdx.x * blockDim.x + threadIdx.x) >> 5;
    if (n >= NN) return;
    int lane = threadIdx.x & 31;

    float4 c = g_sc2[n];
    float gm0 = funkey(g_gk2[0]), gm1 = funkey(g_gk2[1]);
    float B0 = lrelu(gm0 + c.z), B1 = lrelu(gm1 + c.w);
    float p0s = __expf(lrelu(c.x + c.z) - B0);
    float p1s = __expf(lrelu(c.y + c.w) - B1);

    float ps = (lane < 13) ? p0s : p1s;
    float acc = ps * g_hL[n * 32 + lane];   // lanes >=26 read zero pad
    float den0 = (lane == 0) ? p0s : 0.f;
    float den1 = (lane == 0) ? p1s : 0.f;

    int start = (int)g_row[n], end = (int)g_row[n + 1];
    for (int e0 = start; e0 < end; e0 += 32) {
        int idx = e0 + lane;
        int s = 0;
        float pl0 = 0.f, pl1 = 0.f;
        if (idx < end) {
            s = g_adj[idx];
            float4 cs = g_sc2[s];
            pl0 = __expf(lrelu(cs.x + c.z) - B0);
            pl1 = __expf(lrelu(cs.y + c.w) - B1);
        }
        den0 += pl0; den1 += pl1;
        int cnt = min(32, end - e0);
#pragma unroll 4
        for (int j = 0; j < cnt; j++) {
            int   sj = __shfl_sync(0xffffffffu, s, j);
            float q0 = __shfl_sync(0xffffffffu, pl0, j);
            float q1 = __shfl_sync(0xffffffffu, pl1, j);
            float pj = (lane < 13) ? q0 : q1;
            acc += pj * g_hL[sj * 32 + lane];
        }
    }
#pragma unroll
    for (int off = 16; off; off >>= 1) {
        den0 += __shfl_xor_sync(0xffffffffu, den0, off);
        den1 += __shfl_xor_sync(0xffffffffu, den1, off);
    }
    float inv = (lane < 13) ? (1.f / den0) : (1.f / den1);
    float val = acc * inv;
    float v13 = __shfl_down_sync(0xffffffffu, val, 13);
    float sig = 0.f;
    if (lane < CO) {
        float z = 0.5f * (val + v13) + b2[lane];
        sig = 1.f / (1.f + __expf(-z));
    }
    float m = 0.f;
#pragma unroll
    for (int j = 0; j < CO; j++) {
        float sj = __shfl_sync(0xffffffffu, sig, j);
        if (lane < CO) {
            float v = sR[lane * CO + j] * sj;
            m = v > m ? v : m;
        }
    }
    if (lane < CO) out[n * CO + lane] = m;
}

// -----------------------------------------------------------------------------
extern "C" void kernel_launch(void* const* d_in, const int* in_sizes, int n_in,
                              void* d_out, int out_size) {
    const float* x   = (const float*)d_in[0];
    const int*   ei  = (const int*)  d_in[1];
    const float* R   = (const float*)d_in[2];
    const float* W1  = (const float*)d_in[3];
    const float* a1s = (const float*)d_in[4];
    const float* a1d = (const float*)d_in[5];
    const float* b1  = (const float*)d_in[6];
    const float* W2  = (const float*)d_in[7];
    const float* a2s = (const float*)d_in[8];
    const float* a2d = (const float*)d_in[9];
    const float* b2  = (const float*)d_in[10];
    float* out = (float*)d_out;

    const int* src = ei;
    const int* dst = ei + NE;

    const int TB = 256;
    int nbN = (NN + TB - 1) / TB;
    int nbE = (NE + TB - 1) / TB;
    int nbW = (int)(((long long)NN * 32 + TB - 1) / TB);

    initZ<<<nbN, TB>>>();
    nodeA1<<<nbN, TB>>>(x, W1, a1s, a1d);
    hist<<<nbE, TB>>>(dst);
    scanA<<<NB_SCAN, TB>>>();
    scanB<<<1, 128>>>();
    scanC<<<NB_SCAN, TB>>>();
    scatterE<<<nbE, TB>>>(src, dst);
    agg1<<<nbW, TB>>>(b1);
    nodeA2<<<nbN, TB>>>(W2, a2s, a2d);
    agg2<<<nbW, TB>>>(b2, R, out);
}

// round 5
// speedup vs baseline: 3.4610x; 1.1248x over previous
#include <cuda_runtime.h>
#include <cuda_fp16.h>

#define NN 100000
#define NE 3200000
#define CO 13
#define NEG 0.2f
#define NB_SCAN 98          // ceil(NN/1024)

// ---------------- scratch ----------------------------------------------------
__device__ __align__(16) __half2 g_h1h[NN * 32];  // layer1 features [N,2,32] as half2
__device__ __align__(16) float4  g_sc1[NN];       // (ss0, ss1, sd0, sd1)
__device__ __align__(16) float2  g_ss1[NN];       // (ss0, ss1) src-score gather copy
__device__ __align__(16) float   g_h2[NN * 64];   // relu(layer1 out), fp32
__device__ __align__(16) __half  g_hLh[NN * 32];  // layer2 features, padded 26->32, half
__device__ __align__(16) float4  g_sc2[NN];
__device__ __align__(16) float2  g_ss2[NN];
__device__ unsigned g_gk1[2], g_gk2[2];           // global max s_src keys

__device__ unsigned g_deg[NN];
__device__ unsigned g_row[NN + 1];
__device__ unsigned g_cur[NN];
__device__ unsigned g_part[NB_SCAN];
__device__ unsigned g_poff[NB_SCAN];
__device__ int      g_adj[NE];                    // src ids grouped by dst

__device__ __forceinline__ float lrelu(float v) { return v > 0.f ? v : NEG * v; }

__device__ __forceinline__ unsigned fkey(float f) {
    unsigned u = __float_as_uint(f);
    return ((int)u >= 0) ? (u | 0x80000000u) : ~u;
}
__device__ __forceinline__ float funkey(unsigned k) {
    return (k & 0x80000000u) ? __uint_as_float(k & 0x7fffffffu) : __uint_as_float(~k);
}

// ---------------- init: zero deg + global keys -------------------------------
__global__ void initZ() {
    int i = blockIdx.x * blockDim.x + threadIdx.x;
    if (i < NN) g_deg[i] = 0u;
    if (i < 2) { g_gk1[i] = 0u; g_gk2[i] = 0u; }
}

// ---------------- CSR build --------------------------------------------------
__global__ void hist(const int* __restrict__ dst) {
    int e = blockIdx.x * blockDim.x + threadIdx.x;
    if (e < NE) atomicAdd(&g_deg[dst[e]], 1u);
}

__global__ void scanA() {
    __shared__ unsigned sm[8];
    int b = blockIdx.x, t = threadIdx.x;
    int base = b * 1024 + t * 4;
    unsigned s = 0;
#pragma unroll
    for (int k = 0; k < 4; k++) if (base + k < NN) s += g_deg[base + k];
#pragma unroll
    for (int off = 16; off; off >>= 1) s += __shfl_xor_sync(0xffffffffu, s, off);
    if ((t & 31) == 0) sm[t >> 5] = s;
    __syncthreads();
    if (t == 0) {
        unsigned tot = 0;
#pragma unroll
        for (int i = 0; i < 8; i++) tot += sm[i];
        g_part[b] = tot;
    }
}

__global__ void scanB() {
    __shared__ unsigned sh[128];
    int t = threadIdx.x;
    unsigned v = (t < NB_SCAN) ? g_part[t] : 0u;
    sh[t] = v;
    __syncthreads();
    for (int off = 1; off < 128; off <<= 1) {
        unsigned add = (t >= off) ? sh[t - off] : 0u;
        __syncthreads();
        sh[t] += add;
        __syncthreads();
    }
    if (t < NB_SCAN) g_poff[t] = sh[t] - v;
    if (t == 0) g_row[NN] = NE;
}

__global__ void scanC() {
    __shared__ unsigned wsum[8];
    __shared__ unsigned woff[8];
    int b = blockIdx.x, t = threadIdx.x;
    int lane = t & 31, wid = t >> 5;
    int base = b * 1024 + t * 4;
    unsigned v[4];
#pragma unroll
    for (int k = 0; k < 4; k++) v[k] = (base + k < NN) ? g_deg[base + k] : 0u;
    unsigned tot = v[0] + v[1] + v[2] + v[3];
    unsigned inc = tot;
#pragma unroll
    for (int off = 1; off < 32; off <<= 1) {
        unsigned nb = __shfl_up_sync(0xffffffffu, inc, off);
        if (lane >= off) inc += nb;
    }
    if (lane == 31) wsum[wid] = inc;
    __syncthreads();
    if (t == 0) {
        unsigned r = 0;
#pragma unroll
        for (int i = 0; i < 8; i++) { woff[i] = r; r += wsum[i]; }
    }
    __syncthreads();
    unsigned r = inc - tot + woff[wid] + g_poff[b];
#pragma unroll
    for (int k = 0; k < 4; k++) {
        if (base + k < NN) { g_row[base + k] = r; g_cur[base + k] = r; r += v[k]; }
    }
}

__global__ void scatterE(const int* __restrict__ src, const int* __restrict__ dst) {
    int e = blockIdx.x * blockDim.x + threadIdx.x;
    if (e >= NE) return;
    unsigned pos = atomicAdd(&g_cur[dst[e]], 1u);
    g_adj[pos] = src[e];
}

// ---------------- layer 1 node prologue --------------------------------------
__global__ void __launch_bounds__(256) nodeA1(const float* __restrict__ x,
                                              const float* __restrict__ W1,
                                              const float* __restrict__ a1s,
                                              const float* __restrict__ a1d) {
    __shared__ float sW[12 * 64];
    __shared__ float sA[128];
    __shared__ float sm0[8], sm1[8];
    for (int i = threadIdx.x; i < 768; i += blockDim.x) sW[i] = W1[i];
    if (threadIdx.x < 64) { sA[threadIdx.x] = a1s[threadIdx.x]; sA[64 + threadIdx.x] = a1d[threadIdx.x]; }
    __syncthreads();
    int n = blockIdx.x * blockDim.x + threadIdx.x;
    float ss0 = -1e30f, ss1 = -1e30f;

    if (n < NN) {
        float xv[12];
#pragma unroll
        for (int i = 0; i < 12; i++) xv[i] = x[n * 12 + i];
        float h[64];
#pragma unroll
        for (int j = 0; j < 64; j++) {
            float acc = 0.f;
#pragma unroll
            for (int i = 0; i < 12; i++) acc += xv[i] * sW[i * 64 + j];
            h[j] = acc;
        }
        float sd0 = 0.f, sd1 = 0.f;
        ss0 = 0.f; ss1 = 0.f;
#pragma unroll
        for (int f = 0; f < 32; f++) {
            ss0 += h[f] * sA[f];
            ss1 += h[32 + f] * sA[32 + f];
            sd0 += h[f] * sA[64 + f];
            sd1 += h[32 + f] * sA[96 + f];
        }
        // pack to half2, store as 4x uint4 (16B stores)
        uint4* hv = reinterpret_cast<uint4*>(g_h1h + n * 32);
#pragma unroll
        for (int q = 0; q < 4; q++) {
            uint4 pk;
            *reinterpret_cast<__half2*>(&pk.x) = __floats2half2_rn(h[16 * q + 0],  h[16 * q + 1]);
            *reinterpret_cast<__half2*>(&pk.y) = __floats2half2_rn(h[16 * q + 2],  h[16 * q + 3]);
            *reinterpret_cast<__half2*>(&pk.z) = __floats2half2_rn(h[16 * q + 4],  h[16 * q + 5]);
            *reinterpret_cast<__half2*>(&pk.w) = __floats2half2_rn(h[16 * q + 6],  h[16 * q + 7]);
            uint4 pk2;
            *reinterpret_cast<__half2*>(&pk2.x) = __floats2half2_rn(h[16 * q + 8],  h[16 * q + 9]);
            *reinterpret_cast<__half2*>(&pk2.y) = __floats2half2_rn(h[16 * q + 10], h[16 * q + 11]);
            *reinterpret_cast<__half2*>(&pk2.z) = __floats2half2_rn(h[16 * q + 12], h[16 * q + 13]);
            *reinterpret_cast<__half2*>(&pk2.w) = __floats2half2_rn(h[16 * q + 14], h[16 * q + 15]);
            hv[2 * q] = pk;
            hv[2 * q + 1] = pk2;
        }
        g_sc1[n] = make_float4(ss0, ss1, sd0, sd1);
        g_ss1[n] = make_float2(ss0, ss1);
    }
#pragma unroll
    for (int off = 16; off; off >>= 1) {
        ss0 = fmaxf(ss0, __shfl_xor_sync(0xffffffffu, ss0, off));
        ss1 = fmaxf(ss1, __shfl_xor_sync(0xffffffffu, ss1, off));
    }
    int wid = threadIdx.x >> 5;
    if ((threadIdx.x & 31) == 0) { sm0[wid] = ss0; sm1[wid] = ss1; }
    __syncthreads();
    if (threadIdx.x == 0) {
        float a = sm0[0], b = sm1[0];
#pragma unroll
        for (int i = 1; i < 8; i++) { a = fmaxf(a, sm0[i]); b = fmaxf(b, sm1[i]); }
        atomicMax(&g_gk1[0], fkey(a));
        atomicMax(&g_gk1[1], fkey(b));
    }
}

// ---------------- layer1 CSR aggregate: warp per node, fused epilogue --------
__global__ void __launch_bounds__(256) agg1(const float* __restrict__ b1) {
    int n = (blockIdx.x * blockDim.x + threadIdx.x) >> 5;
    if (n >= NN) return;
    int lane = threadIdx.x & 31;

    float4 c = g_sc1[n];
    float gm0 = funkey(g_gk1[0]), gm1 = funkey(g_gk1[1]);
    float B0 = lrelu(gm0 + c.z), B1 = lrelu(gm1 + c.w);
    float p0s = __expf(lrelu(c.x + c.z) - B0);
    float p1s = __expf(lrelu(c.y + c.w) - B1);

    float ps = (lane < 16) ? p0s : p1s;
    float2 hs = __half22float2(g_h1h[n * 32 + lane]);
    float accx = ps * hs.x, accy = ps * hs.y;
    float den0 = (lane == 0) ? p0s : 0.f;
    float den1 = (lane == 0) ? p1s : 0.f;

    int start = (int)g_row[n], end = (int)g_row[n + 1];
    for (int e0 = start; e0 < end; e0 += 32) {
        int idx = e0 + lane;
        int s = 0;
        float pl0 = 0.f, pl1 = 0.f;
        if (idx < end) {
            s = g_adj[idx];
            float2 cs = g_ss1[s];
            pl0 = __expf(lrelu(cs.x + c.z) - B0);
            pl1 = __expf(lrelu(cs.y + c.w) - B1);
        }
        den0 += pl0; den1 += pl1;
        int cnt = min(32, end - e0);
#pragma unroll 4
        for (int j = 0; j < cnt; j++) {
            int   sj = __shfl_sync(0xffffffffu, s, j);
            float q0 = __shfl_sync(0xffffffffu, pl0, j);
            float q1 = __shfl_sync(0xffffffffu, pl1, j);
            float pj = (lane < 16) ? q0 : q1;
            float2 v = __half22float2(g_h1h[sj * 32 + lane]);
            accx += pj * v.x;
            accy += pj * v.y;
        }
    }
#pragma unroll
    for (int off = 16; off; off >>= 1) {
        den0 += __shfl_xor_sync(0xffffffffu, den0, off);
        den1 += __shfl_xor_sync(0xffffffffu, den1, off);
    }
    float inv = (lane < 16) ? (1.f / den0) : (1.f / den1);
    float o0 = accx * inv + b1[2 * lane];
    float o1 = accy * inv + b1[2 * lane + 1];
    float2 o = make_float2(o0 > 0.f ? o0 : 0.f, o1 > 0.f ? o1 : 0.f);
    *(float2*)(g_h2 + n * 64 + 2 * lane) = o;
}

// ---------------- layer 2 node prologue (W2 matmul + scores) -----------------
__global__ void __launch_bounds__(256) nodeA2(const float* __restrict__ W2,
                                              const float* __restrict__ a2s,
                                              const float* __restrict__ a2d) {
    __shared__ float sW[64 * 26];
    __shared__ float sA[52];
    __shared__ float sm0[8], sm1[8];
    for (int i = threadIdx.x; i < 64 * 26; i += blockDim.x) sW[i] = W2[i];
    if (threadIdx.x < 26) { sA[threadIdx.x] = a2s[threadIdx.x]; sA[26 + threadIdx.x] = a2d[threadIdx.x]; }
    __syncthreads();
    int n = blockIdx.x * blockDim.x + threadIdx.x;
    float ms0 = -1e30f, ms1 = -1e30f;

    if (n < NN) {
        float acc[26];
#pragma unroll
        for (int j = 0; j < 26; j++) acc[j] = 0.f;
        const float4* h2v = reinterpret_cast<const float4*>(g_h2) + n * 16;
#pragma unroll
        for (int q = 0; q < 16; q++) {
            float4 hv = h2v[q];
#pragma unroll
            for (int j = 0; j < 26; j++) {
                acc[j] += hv.x * sW[(4 * q) * 26 + j];
                acc[j] += hv.y * sW[(4 * q + 1) * 26 + j];
                acc[j] += hv.z * sW[(4 * q + 2) * 26 + j];
                acc[j] += hv.w * sW[(4 * q + 3) * 26 + j];
            }
        }
        float ss0 = 0.f, ss1 = 0.f, sd0 = 0.f, sd1 = 0.f;
#pragma unroll
        for (int f = 0; f < 13; f++) {
            ss0 += acc[f] * sA[f];
            ss1 += acc[13 + f] * sA[13 + f];
            sd0 += acc[f] * sA[26 + f];
            sd1 += acc[13 + f] * sA[39 + f];
        }
        float tmp[32];
#pragma unroll
        for (int j = 0; j < 26; j++) tmp[j] = acc[j];
#pragma unroll
        for (int j = 26; j < 32; j++) tmp[j] = 0.f;
        // pack 32 halves = 4x uint2 (8B) -> use 2x uint4
        uint4* hv4 = reinterpret_cast<uint4*>(g_hLh + n * 32);
#pragma unroll
        for (int q = 0; q < 2; q++) {
            uint4 pk;
            *reinterpret_cast<__half2*>(&pk.x) = __floats2half2_rn(tmp[16 * q + 0],  tmp[16 * q + 1]);
            *reinterpret_cast<__half2*>(&pk.y) = __floats2half2_rn(tmp[16 * q + 2],  tmp[16 * q + 3]);
            *reinterpret_cast<__half2*>(&pk.z) = __floats2half2_rn(tmp[16 * q + 4],  tmp[16 * q + 5]);
            *reinterpret_cast<__half2*>(&pk.w) = __floats2half2_rn(tmp[16 * q + 6],  tmp[16 * q + 7]);
            uint4 pk2;
            *reinterpret_cast<__half2*>(&pk2.x) = __floats2half2_rn(tmp[16 * q + 8],  tmp[16 * q + 9]);
            *reinterpret_cast<__half2*>(&pk2.y) = __floats2half2_rn(tmp[16 * q + 10], tmp[16 * q + 11]);
            *reinterpret_cast<__half2*>(&pk2.z) = __floats2half2_rn(tmp[16 * q + 12], tmp[16 * q + 13]);
            *reinterpret_cast<__half2*>(&pk2.w) = __floats2half2_rn(tmp[16 * q + 14], tmp[16 * q + 15]);
            hv4[2 * q] = pk;
            hv4[2 * q + 1] = pk2;
        }
        g_sc2[n] = make_float4(ss0, ss1, sd0, sd1);
        g_ss2[n] = make_float2(ss0, ss1);
        ms0 = ss0; ms1 = ss1;
    }
#pragma unroll
    for (int off = 16; off; off >>= 1) {
        ms0 = fmaxf(ms0, __shfl_xor_sync(0xffffffffu, ms0, off));
        ms1 = fmaxf(ms1, __shfl_xor_sync(0xffffffffu, ms1, off));
    }
    int wid = threadIdx.x >> 5;
    if ((threadIdx.x & 31) == 0) { sm0[wid] = ms0; sm1[wid] = ms1; }
    __syncthreads();
    if (threadIdx.x == 0) {
        float a = sm0[0], b = sm1[0];
#pragma unroll
        for (int i = 1; i < 8; i++) { a = fmaxf(a, sm0[i]); b = fmaxf(b, sm1[i]); }
        atomicMax(&g_gk2[0], fkey(a));
        atomicMax(&g_gk2[1], fkey(b));
    }
}

// ---------------- layer2 CSR aggregate + sigmoid + constraint (fused) --------
__global__ void __launch_bounds__(256) agg2(const float* __restrict__ b2,
                                            const float* __restrict__ R,
                                            float* __restrict__ out) {
    __shared__ float sR[CO * CO];
    if (threadIdx.x < CO * CO) sR[threadIdx.x] = R[threadIdx.x];
    __syncthreads();
    int n = (blockIdx.x * blockDim.x + threadIdx.x) >> 5;
    if (n >= NN) return;
    int lane = threadIdx.x & 31;

    float4 c = g_sc2[n];
    float gm0 = funkey(g_gk2[0]), gm1 = funkey(g_gk2[1]);
    float B0 = lrelu(gm0 + c.z), B1 = lrelu(gm1 + c.w);
    float p0s = __expf(lrelu(c.x + c.z) - B0);
    float p1s = __expf(lrelu(c.y + c.w) - B1);

    float ps = (lane < 13) ? p0s : p1s;
    float acc = ps * __half2float(g_hLh[n * 32 + lane]);  // lanes >=26 read zero pad
    float den0 = (lane == 0) ? p0s : 0.f;
    float den1 = (lane == 0) ? p1s : 0.f;

    int start = (int)g_row[n], end = (int)g_row[n + 1];
    for (int e0 = start; e0 < end; e0 += 32) {
        int idx = e0 + lane;
        int s = 0;
        float pl0 = 0.f, pl1 = 0.f;
        if (idx < end) {
            s = g_adj[idx];
            float2 cs = g_ss2[s];
            pl0 = __expf(lrelu(cs.x + c.z) - B0);
            pl1 = __expf(lrelu(cs.y + c.w) - B1);
        }
        den0 += pl0; den1 += pl1;
        int cnt = min(32, end - e0);
#pragma unroll 4
        for (int j = 0; j < cnt; j++) {
            int   sj = __shfl_sync(0xffffffffu, s, j);
            float q0 = __shfl_sync(0xffffffffu, pl0, j);
            float q1 = __shfl_sync(0xffffffffu, pl1, j);
            float pj = (lane < 13) ? q0 : q1;
            acc += pj * __half2float(g_hLh[sj * 32 + lane]);
        }
    }
#pragma unroll
    for (int off = 16; off; off >>= 1) {
        den0 += __shfl_xor_sync(0xffffffffu, den0, off);
        den1 += __shfl_xor_sync(0xffffffffu, den1, off);
    }
    float inv = (lane < 13) ? (1.f / den0) : (1.f / den1);
    float val = acc * inv;
    float v13 = __shfl_down_sync(0xffffffffu, val, 13);
    float sig = 0.f;
    if (lane < CO) {
        float z = 0.5f * (val + v13) + b2[lane];
        sig = 1.f / (1.f + __expf(-z));
    }
    float m = 0.f;
#pragma unroll
    for (int j = 0; j < CO; j++) {
        float sj = __shfl_sync(0xffffffffu, sig, j);
        if (lane < CO) {
            float v = sR[lane * CO + j] * sj;
            m = v > m ? v : m;
        }
    }
    if (lane < CO) out[n * CO + lane] = m;
}

// -----------------------------------------------------------------------------
extern "C" void kernel_launch(void* const* d_in, const int* in_sizes, int n_in,
                              void* d_out, int out_size) {
    const float* x   = (const float*)d_in[0];
    const int*   ei  = (const int*)  d_in[1];
    const float* R   = (const float*)d_in[2];
    const float* W1  = (const float*)d_in[3];
    const float* a1s = (const float*)d_in[4];
    const float* a1d = (const float*)d_in[5];
    const float* b1  = (const float*)d_in[6];
    const float* W2  = (const float*)d_in[7];
    const float* a2s = (const float*)d_in[8];
    const float* a2d = (const float*)d_in[9];
    const float* b2  = (const float*)d_in[10];
    float* out = (float*)d_out;

    const int* src = ei;
    const int* dst = ei + NE;

    const int TB = 256;
    int nbN = (NN + TB - 1) / TB;
    int nbE = (NE + TB - 1) / TB;
    int nbW = (int)(((long long)NN * 32 + TB - 1) / TB);

    initZ<<<nbN, TB>>>();
    nodeA1<<<nbN, TB>>>(x, W1, a1s, a1d);
    hist<<<nbE, TB>>>(dst);
    scanA<<<NB_SCAN, TB>>>();
    scanB<<<1, 128>>>();
    scanC<<<NB_SCAN, TB>>>();
    scatterE<<<nbE, TB>>>(src, dst);
    agg1<<<nbW, TB>>>(b1);
    nodeA2<<<nbN, TB>>>(W2, a2s, a2d);
    agg2<<<nbW, TB>>>(b2, R, out);
}